// round 5
// baseline (speedup 1.0000x reference)
#include <cuda_runtime.h>

#define NCLS 80
#define NB 16
#define NQ 300
#define NT 50
#define HDIM 128
#define HM_BLOCKS 1184
#define THREADS 256
#define NPAIR (NB * NT)        // 800
#define HSLOTS 1024
#define NWORK (HM_BLOCKS + NB) // 1200 worker blocks
#define NBLK (NWORK + 1)

__device__ double g_hm  = 0.0;
__device__ double g_cen = 0.0;
__device__ double g_ced = 0.0;
__device__ unsigned g_done = 0;

__device__ __forceinline__ float focal_neg(float x) {
    float t   = __expf(-fabsf(x));
    float omp = 1.0f + t;
    float r   = __fdividef(1.0f, omp);
    float L   = __logf(omp);
    float sp  = fmaxf(x, 0.0f) + L;
    float s   = (x >= 0.0f ? 1.0f : t) * r;
    return sp * s * s;
}

__device__ __forceinline__ float focal_delta(float x) {
    float t   = expf(-fabsf(x));
    float L   = log1pf(t);
    float omp = 1.0f + t;
    float sig = (x >= 0.0f ? 1.0f : t) / omp;
    float sp_neg = fmaxf(x, 0.0f) + L;
    float sp_pos = fmaxf(-x, 0.0f) + L;
    float pos = 0.25f * sp_pos * (1.0f - sig) * (1.0f - sig);
    float neg = 0.75f * sp_neg * sig * sig;
    return pos - neg;
}

__device__ __forceinline__ int hslot(unsigned k) {
    return (int)((k * 2654435761u) >> 11) & (HSLOTS - 1);
}

__global__ void __launch_bounds__(THREADS)
k_all(const float4* __restrict__ hm4, long nvec,
      const float* __restrict__ logits,
      const float* __restrict__ pred_boxes,
      const float* __restrict__ tgt_boxes,
      const float* __restrict__ tgt_sizes,
      const int*   __restrict__ src_idx,
      const int*   __restrict__ tgt_idx,
      const int*   __restrict__ tgt_labels,
      const float* __restrict__ ew,
      const float* __restrict__ heatmap,
      const float* __restrict__ box_map,
      float* __restrict__ out)
{
    __shared__ int pk[HSLOTS], pmn[HSLOTS], pmx[HSLOTS];
    __shared__ int gkk[HSLOTS], gmn[HSLOTS];
    __shared__ float sred[THREADS / 32];
    __shared__ int tcls[NQ];
    __shared__ float sn[THREADS / 32], sd[THREADS / 32];
    __shared__ float s_l1, s_gi, s_bc, s_hc;
    __shared__ int s_np;

    int tid = threadIdx.x;
    int bid = blockIdx.x;

    if (bid < HM_BLOCKS) {
        // ---- dense focal(target=0) over the heatmap ----
        float acc = 0.0f;
        long stride = (long)HM_BLOCKS * THREADS;
        long i = (long)bid * THREADS + tid;
        #pragma unroll 4
        for (; i < nvec; i += stride) {
            float4 v = hm4[i];
            acc += focal_neg(v.x);
            acc += focal_neg(v.y);
            acc += focal_neg(v.z);
            acc += focal_neg(v.w);
        }
        #pragma unroll
        for (int o = 16; o; o >>= 1) acc += __shfl_xor_sync(0xffffffffu, acc, o);
        if ((tid & 31) == 0) sred[tid >> 5] = acc;
        __syncthreads();
        if (tid == 0) {
            double s = 0.0;
            for (int w = 0; w < THREADS / 32; w++) s += (double)sred[w];
            atomicAdd(&g_hm, 0.75 * s);
            __threadfence();
            atomicAdd(&g_done, 1u);
        }
    } else if (bid < NWORK) {
        // ---- CE: one block per batch ----
        int b = bid - HM_BLOCKS;
        for (int q = tid; q < NQ; q += THREADS) tcls[q] = NCLS;
        __syncthreads();
        if (tid < NT) {
            int si = src_idx[b * NT + tid];
            int ti = tgt_idx[b * NT + tid];
            tcls[si] = tgt_labels[b * NT + ti];
        }
        __syncthreads();
        int warp = tid >> 5, lane = tid & 31;
        float an = 0.0f, ad = 0.0f;
        for (int q = warp; q < NQ; q += THREADS / 32) {
            const float* row = logits + (long)(b * NQ + q) * (NCLS + 1);
            float v0 = row[lane];
            float v1 = row[lane + 32];
            float v2 = (lane < 17) ? row[lane + 64] : -1e30f;
            float m = fmaxf(fmaxf(v0, v1), v2);
            #pragma unroll
            for (int o = 16; o; o >>= 1) m = fmaxf(m, __shfl_xor_sync(0xffffffffu, m, o));
            float s = __expf(v0 - m) + __expf(v1 - m) + ((lane < 17) ? __expf(v2 - m) : 0.0f);
            #pragma unroll
            for (int o = 16; o; o >>= 1) s += __shfl_xor_sync(0xffffffffu, s, o);
            if (lane == 0) {
                int c = tcls[q];
                float nll = m + __logf(s) - row[c];
                float w = ew[c];
                an += w * nll;
                ad += w;
            }
        }
        if (lane == 0) { sn[warp] = an; sd[warp] = ad; }
        __syncthreads();
        if (tid == 0) {
            double n = 0.0, d = 0.0;
            for (int w = 0; w < THREADS / 32; w++) { n += (double)sn[w]; d += (double)sd[w]; }
            atomicAdd(&g_cen, n);
            atomicAdd(&g_ced, d);
            __threadfence();
            atomicAdd(&g_done, 1u);
        }
    } else {
        // ---- pair losses + sparse dedup + finalize ----
        for (int i = tid; i < HSLOTS; i += THREADS) {
            pk[i] = -1; pmn[i] = 0x7fffffff; pmx[i] = -1;
            gkk[i] = -1; gmn[i] = 0x7fffffff;
        }
        if (tid == 0) { s_l1 = 0.f; s_gi = 0.f; s_bc = 0.f; s_hc = 0.f; s_np = 0; }
        __syncthreads();

        float l1 = 0.f, gi = 0.f, bc = 0.f, hc = 0.f;
        int npc = 0;

        // phase A: pair losses + hash inserts (ordering key = pair index p)
        for (int p = tid; p < NPAIR; p += THREADS) {
            int b = p / NT;
            float iw = 1.0f / tgt_sizes[b * 2 + 1];  // w_im = sizes[:,1]
            float ih = 1.0f / tgt_sizes[b * 2 + 0];  // h_im = sizes[:,0]

            int si = src_idx[p];
            int ti = tgt_idx[p];
            const float* sb = pred_boxes + (long)(b * NQ + si) * 4;
            float scx = sb[0], scy = sb[1], sw = sb[2], sh = sb[3];
            const float* tb = tgt_boxes + (long)(b * NT + ti) * 4;
            float tx1 = tb[0] * iw, ty1 = tb[1] * ih, tx2 = tb[2] * iw, ty2 = tb[3] * ih;
            float tcx = (tx1 + tx2) * 0.5f, tcy = (ty1 + ty2) * 0.5f;
            float tw = tx2 - tx1, th = ty2 - ty1;
            l1 += fabsf(scx - tcx) + fabsf(scy - tcy) + fabsf(sw - tw) + fabsf(sh - th);

            float ax1 = scx - 0.5f * sw, ay1 = scy - 0.5f * sh;
            float ax2 = scx + 0.5f * sw, ay2 = scy + 0.5f * sh;
            float bx1 = tcx - 0.5f * tw, by1 = tcy - 0.5f * th;
            float bx2 = tcx + 0.5f * tw, by2 = tcy + 0.5f * th;
            float aa = (ax2 - ax1) * (ay2 - ay1);
            float ab = (bx2 - bx1) * (by2 - by1);
            float wi = fmaxf(fminf(ax2, bx2) - fmaxf(ax1, bx1), 0.f);
            float hi = fmaxf(fminf(ay2, by2) - fmaxf(ay1, by1), 0.f);
            float inter = wi * hi;
            float uni = aa + ab - inter;
            float iou = inter / uni;
            float cw = fmaxf(fmaxf(ax2, bx2) - fminf(ax1, bx1), 0.f);
            float ch = fmaxf(fmaxf(ay2, by2) - fminf(ay1, by1), 0.f);
            float ac = cw * ch;
            gi += 1.0f - (iou - (ac - uni) / ac);

            const float* ob = tgt_boxes + (long)p * 4;
            float cxn = (ob[0] + ob[2]) * 0.5f * iw;
            float cyn = (ob[1] + ob[3]) * 0.5f * ih;
            int gx = min(max((int)(cxn * (float)HDIM), 0), HDIM - 1);
            int gy = min(max((int)(cyn * (float)HDIM), 0), HDIM - 1);
            int lf = tgt_labels[p];

            int kp = (b << 14) | (gy << 7) | gx;
            int kg = (b << 21) | (lf << 14) | (gy << 7) | gx;

            int slot = hslot((unsigned)kp);
            while (true) {
                int old = atomicCAS(&pk[slot], -1, kp);
                if (old == -1 || old == kp) {
                    atomicMin(&pmn[slot], p);
                    atomicMax(&pmx[slot], p);
                    break;
                }
                slot = (slot + 1) & (HSLOTS - 1);
            }
            slot = hslot((unsigned)kg);
            while (true) {
                int old = atomicCAS(&gkk[slot], -1, kg);
                if (old == -1 || old == kg) {
                    atomicMin(&gmn[slot], p);
                    break;
                }
                slot = (slot + 1) & (HSLOTS - 1);
            }
        }
        __syncthreads();

        // phase B: dedup winners perform sparse corrections
        for (int p = tid; p < NPAIR; p += THREADS) {
            int b = p / NT;
            float iw = 1.0f / tgt_sizes[b * 2 + 1];
            float ih = 1.0f / tgt_sizes[b * 2 + 0];
            const float* ob = tgt_boxes + (long)p * 4;
            float ox1 = ob[0] * iw, oy1 = ob[1] * ih;
            float ox2 = ob[2] * iw, oy2 = ob[3] * ih;
            float bf0 = (ox1 + ox2) * 0.5f;
            float bf1 = (oy1 + oy2) * 0.5f;
            float bf2 = ox2 - ox1;
            float bf3 = oy2 - oy1;
            int gx = min(max((int)(bf0 * (float)HDIM), 0), HDIM - 1);
            int gy = min(max((int)(bf1 * (float)HDIM), 0), HDIM - 1);
            int lf = tgt_labels[p];

            int kp = (b << 14) | (gy << 7) | gx;
            int kg = (b << 21) | (lf << 14) | (gy << 7) | gx;

            int slot = hslot((unsigned)kp);
            while (pk[slot] != kp) slot = (slot + 1) & (HSLOTS - 1);
            if (pmn[slot] == p) npc += 1;
            if (pmx[slot] == p) {  // last write wins for box_target
                long base = ((long)b * 4) * HDIM * HDIM + (long)gy * HDIM + gx;
                bc += fabsf(box_map[base                  ] - bf0);
                bc += fabsf(box_map[base + 1L * HDIM * HDIM] - bf1);
                bc += fabsf(box_map[base + 2L * HDIM * HDIM] - bf2);
                bc += fabsf(box_map[base + 3L * HDIM * HDIM] - bf3);
            }
            slot = hslot((unsigned)kg);
            while (gkk[slot] != kg) slot = (slot + 1) & (HSLOTS - 1);
            if (gmn[slot] == p) {  // distinct positive heatmap cell
                float x = heatmap[(((long)b * NCLS + lf) * HDIM + gy) * HDIM + gx];
                hc += focal_delta(x);
            }
        }

        // block reduce
        #pragma unroll
        for (int o = 16; o; o >>= 1) {
            l1  += __shfl_xor_sync(0xffffffffu, l1, o);
            gi  += __shfl_xor_sync(0xffffffffu, gi, o);
            bc  += __shfl_xor_sync(0xffffffffu, bc, o);
            hc  += __shfl_xor_sync(0xffffffffu, hc, o);
            npc += __shfl_xor_sync(0xffffffffu, npc, o);
        }
        if ((tid & 31) == 0) {
            atomicAdd(&s_l1, l1);
            atomicAdd(&s_gi, gi);
            atomicAdd(&s_bc, bc);
            atomicAdd(&s_hc, hc);
            atomicAdd(&s_np, npc);
        }
        __syncthreads();

        if (tid == 0) {
            // wait for all worker blocks (heatmap + CE)
            volatile unsigned* dp = &g_done;
            while (*dp < (unsigned)NWORK) __nanosleep(200);
            __threadfence();

            double cen = g_cen, ced = g_ced, hmb = g_hm;
            g_cen = 0.0; g_ced = 0.0; g_hm = 0.0;  // reset for next replay
            g_done = 0;
            double ce   = cen / ced;
            double bbox = (double)s_l1 / (double)NPAIR;
            double giou = (double)s_gi / (double)NPAIR;
            double np   = (double)(s_np > 0 ? s_np : 1);
            double hml  = (hmb + (double)s_hc) / np;
            double bxl  = (double)s_bc / np;
            double aux  = hml + 5.0 * bxl;
            out[0] = (float)ce;
            out[1] = (float)bbox;
            out[2] = (float)giou;
            out[3] = (float)aux;
            out[4] = (float)(1.0 * ce + 5.0 * bbox + 2.0 * giou + 1.0 * aux);
        }
    }
}

extern "C" void kernel_launch(void* const* d_in, const int* in_sizes, int n_in,
                              void* d_out, int out_size)
{
    const float* pred_logits  = (const float*)d_in[0];
    const float* pred_boxes   = (const float*)d_in[1];
    const float* heatmap      = (const float*)d_in[2];
    const float* box_map      = (const float*)d_in[3];
    const float* tgt_boxes    = (const float*)d_in[4];
    const int*   tgt_labels   = (const int*)d_in[5];
    const float* tgt_sizes    = (const float*)d_in[6];
    const int*   src_idx      = (const int*)d_in[7];
    const int*   tgt_idx      = (const int*)d_in[8];
    const float* empty_weight = (const float*)d_in[9];
    float* out = (float*)d_out;

    long nvec = (long)in_sizes[2] / 4;

    k_all<<<NBLK, THREADS>>>((const float4*)heatmap, nvec,
                             pred_logits, pred_boxes, tgt_boxes, tgt_sizes,
                             src_idx, tgt_idx, tgt_labels, empty_weight,
                             heatmap, box_map, out);
}

// round 8
// speedup vs baseline: 1.5228x; 1.5228x over previous
#include <cuda_runtime.h>

#define NCLS 80
#define NB 16
#define NQ 300
#define NT 50
#define HDIM 128
#define HM_BLOCKS 1168
#define THREADS 256
#define NPAIR (NB * NT)          // 800
#define NBLK (HM_BLOCKS + NB)    // 1184 = 148 SMs * 8 blocks: one full wave

// global accumulators; the finalizing (last) block resets them each
// invocation so graph replays stay deterministic
__device__ double g_hm  = 0.0;
__device__ double g_cen = 0.0;
__device__ double g_ced = 0.0;
__device__ double g_l1  = 0.0;
__device__ double g_gi  = 0.0;
__device__ double g_bc  = 0.0;
__device__ double g_hc  = 0.0;
__device__ int      g_np   = 0;
__device__ unsigned g_done = 0;

// focal loss term for target==0, WITHOUT the 0.75 alpha factor:
//   softplus(x) * sigmoid(x)^2       (3 MUFU ops)
__device__ __forceinline__ float focal_neg(float x) {
    float t   = __expf(-fabsf(x));
    float omp = 1.0f + t;
    float r   = __fdividef(1.0f, omp);
    float L   = __logf(omp);
    float sp  = fmaxf(x, 0.0f) + L;
    float s   = (x >= 0.0f ? 1.0f : t) * r;
    return sp * s * s;
}

// (alpha-weighted positive) - (alpha-weighted negative) at a positive cell
__device__ __forceinline__ float focal_delta(float x) {
    float t   = expf(-fabsf(x));
    float L   = log1pf(t);
    float omp = 1.0f + t;
    float sig = (x >= 0.0f ? 1.0f : t) / omp;
    float sp_neg = fmaxf(x, 0.0f) + L;
    float sp_pos = fmaxf(-x, 0.0f) + L;
    float pos = 0.25f * sp_pos * (1.0f - sig) * (1.0f - sig);
    float neg = 0.75f * sp_neg * sig * sig;
    return pos - neg;
}

// ---------------------------------------------------------------------------
// Single kernel, single wave:
//   blocks [0, HM_BLOCKS)      : dense heatmap focal base sum
//   blocks [HM_BLOCKS, NBLK)   : CE + pair losses + per-batch dedup for batch b
// The LAST block to finish combines everything and writes out[5].
// ---------------------------------------------------------------------------
__global__ void __launch_bounds__(THREADS)
k_all(const float4* __restrict__ hm4, long nvec,
      const float* __restrict__ logits,
      const float* __restrict__ pred_boxes,
      const float* __restrict__ tgt_boxes,
      const float* __restrict__ tgt_sizes,
      const int*   __restrict__ src_idx,
      const int*   __restrict__ tgt_idx,
      const int*   __restrict__ tgt_labels,
      const float* __restrict__ ew,
      const float* __restrict__ heatmap,
      const float* __restrict__ box_map,
      float* __restrict__ out)
{
    __shared__ float sred[THREADS / 32];
    __shared__ int   tcls[NQ];
    __shared__ float sn[THREADS / 32], sd[THREADS / 32];
    __shared__ int   kparr[NT], kgarr[NT];
    __shared__ float s_l1, s_gi, s_bc, s_hc;
    __shared__ int   s_np;

    int tid = threadIdx.x;
    int bid = blockIdx.x;

    if (bid < HM_BLOCKS) {
        // ================ dense focal(target=0) over the heatmap ===========
        float acc = 0.0f;
        long stride = (long)HM_BLOCKS * THREADS;
        long i = (long)bid * THREADS + tid;
        #pragma unroll 4
        for (; i < nvec; i += stride) {
            float4 v = hm4[i];
            acc += focal_neg(v.x);
            acc += focal_neg(v.y);
            acc += focal_neg(v.z);
            acc += focal_neg(v.w);
        }
        #pragma unroll
        for (int o = 16; o; o >>= 1) acc += __shfl_xor_sync(0xffffffffu, acc, o);
        if ((tid & 31) == 0) sred[tid >> 5] = acc;
        __syncthreads();
        if (tid == 0) {
            double s = 0.0;
            for (int w = 0; w < THREADS / 32; w++) s += (double)sred[w];
            atomicAdd(&g_hm, 0.75 * s);
        }
    } else {
        // ================ CE + pairs for batch b ===========================
        int b = bid - HM_BLOCKS;

        // ---- build target classes for CE ----
        for (int q = tid; q < NQ; q += THREADS) tcls[q] = NCLS;
        if (tid == 0) { s_l1 = 0.f; s_gi = 0.f; s_bc = 0.f; s_hc = 0.f; s_np = 0; }
        __syncthreads();
        if (tid < NT) {
            int si = src_idx[b * NT + tid];
            int ti = tgt_idx[b * NT + tid];
            tcls[si] = tgt_labels[b * NT + ti];
        }
        __syncthreads();

        float iw = 1.0f / tgt_sizes[b * 2 + 1];  // w_im = sizes[:,1]
        float ih = 1.0f / tgt_sizes[b * 2 + 0];  // h_im = sizes[:,0]

        // ---- phase A: pair losses + publish dedup keys (one pair/thread) --
        if (tid < NT) {
            int p = b * NT + tid;

            // matched-pair L1 + GIoU
            int si = src_idx[p];
            int ti = tgt_idx[p];
            const float* sb = pred_boxes + (long)(b * NQ + si) * 4;
            float scx = sb[0], scy = sb[1], sw = sb[2], sh = sb[3];
            const float* tb = tgt_boxes + (long)(b * NT + ti) * 4;
            float tx1 = tb[0] * iw, ty1 = tb[1] * ih, tx2 = tb[2] * iw, ty2 = tb[3] * ih;
            float tcx = (tx1 + tx2) * 0.5f, tcy = (ty1 + ty2) * 0.5f;
            float tw = tx2 - tx1, th = ty2 - ty1;
            float l1 = fabsf(scx - tcx) + fabsf(scy - tcy) + fabsf(sw - tw) + fabsf(sh - th);

            float ax1 = scx - 0.5f * sw, ay1 = scy - 0.5f * sh;
            float ax2 = scx + 0.5f * sw, ay2 = scy + 0.5f * sh;
            float bx1 = tcx - 0.5f * tw, by1 = tcy - 0.5f * th;
            float bx2 = tcx + 0.5f * tw, by2 = tcy + 0.5f * th;
            float aa = (ax2 - ax1) * (ay2 - ay1);
            float ab = (bx2 - bx1) * (by2 - by1);
            float wi = fmaxf(fminf(ax2, bx2) - fmaxf(ax1, bx1), 0.f);
            float hi = fmaxf(fminf(ay2, by2) - fmaxf(ay1, by1), 0.f);
            float inter = wi * hi;
            float uni = aa + ab - inter;
            float iou = inter / uni;
            float cw = fmaxf(fmaxf(ax2, bx2) - fminf(ax1, bx1), 0.f);
            float ch = fmaxf(fmaxf(ay2, by2) - fminf(ay1, by1), 0.f);
            float ac = cw * ch;
            float gi = 1.0f - (iou - (ac - uni) / ac);
            atomicAdd(&s_l1, l1);
            atomicAdd(&s_gi, gi);

            // aux positives: ORIGINAL target order within this batch
            const float* ob = tgt_boxes + (long)p * 4;
            float cxn = (ob[0] + ob[2]) * 0.5f * iw;
            float cyn = (ob[1] + ob[3]) * 0.5f * ih;
            int gx = min(max((int)(cxn * (float)HDIM), 0), HDIM - 1);
            int gy = min(max((int)(cyn * (float)HDIM), 0), HDIM - 1);
            int lf = tgt_labels[p];
            kparr[tid] = (gy << 7) | gx;                // pos key (batch-local)
            kgarr[tid] = (lf << 14) | (gy << 7) | gx;   // heatmap key
        }
        __syncthreads();   // publishes kparr/kgarr to the whole block

        // ---- phase B: dedup scan + sparse corrections ---------------------
        if (tid < NT) {
            int p = b * NT + tid;
            const float* ob = tgt_boxes + (long)p * 4;
            float ox1 = ob[0] * iw, oy1 = ob[1] * ih;
            float ox2 = ob[2] * iw, oy2 = ob[3] * ih;
            float bf0 = (ox1 + ox2) * 0.5f;
            float bf1 = (oy1 + oy2) * 0.5f;
            float bf2 = ox2 - ox1;
            float bf3 = oy2 - oy1;
            int gx = min(max((int)(bf0 * (float)HDIM), 0), HDIM - 1);
            int gy = min(max((int)(bf1 * (float)HDIM), 0), HDIM - 1);
            int lf = tgt_labels[p];
            int kp = (gy << 7) | gx;
            int kg = (lf << 14) | (gy << 7) | gx;

            bool first_p = true, last_p = true, first_g = true;
            #pragma unroll 1
            for (int u = 0; u < NT; u++) {
                if (u < tid) {
                    if (kparr[u] == kp) first_p = false;
                    if (kgarr[u] == kg) first_g = false;
                } else if (u > tid) {
                    if (kparr[u] == kp) last_p = false;
                }
            }
            if (first_p) atomicAdd(&s_np, 1);
            if (last_p) {  // last write wins for box_target
                long base = ((long)b * 4) * HDIM * HDIM + (long)gy * HDIM + gx;
                float bcv = fabsf(box_map[base                   ] - bf0)
                          + fabsf(box_map[base + 1L * HDIM * HDIM] - bf1)
                          + fabsf(box_map[base + 2L * HDIM * HDIM] - bf2)
                          + fabsf(box_map[base + 3L * HDIM * HDIM] - bf3);
                atomicAdd(&s_bc, bcv);
            }
            if (first_g) {  // distinct positive heatmap cell
                float x = heatmap[(((long)b * NCLS + lf) * HDIM + gy) * HDIM + gx];
                atomicAdd(&s_hc, focal_delta(x));
            }
        }

        // ---- CE over this batch's 300 rows --------------------------------
        int warp = tid >> 5, lane = tid & 31;
        float an = 0.0f, ad = 0.0f;
        for (int q = warp; q < NQ; q += THREADS / 32) {
            const float* row = logits + (long)(b * NQ + q) * (NCLS + 1);
            float v0 = row[lane];
            float v1 = row[lane + 32];
            float v2 = (lane < 17) ? row[lane + 64] : -1e30f;
            float m = fmaxf(fmaxf(v0, v1), v2);
            #pragma unroll
            for (int o = 16; o; o >>= 1) m = fmaxf(m, __shfl_xor_sync(0xffffffffu, m, o));
            float s = __expf(v0 - m) + __expf(v1 - m) + ((lane < 17) ? __expf(v2 - m) : 0.0f);
            #pragma unroll
            for (int o = 16; o; o >>= 1) s += __shfl_xor_sync(0xffffffffu, s, o);
            if (lane == 0) {
                int c = tcls[q];
                float nll = m + __logf(s) - row[c];
                float w = ew[c];
                an += w * nll;
                ad += w;
            }
        }
        if (lane == 0) { sn[warp] = an; sd[warp] = ad; }
        __syncthreads();
        if (tid == 0) {
            double n = 0.0, d = 0.0;
            for (int w = 0; w < THREADS / 32; w++) { n += (double)sn[w]; d += (double)sd[w]; }
            atomicAdd(&g_cen, n);
            atomicAdd(&g_ced, d);
            atomicAdd(&g_l1, (double)s_l1);
            atomicAdd(&g_gi, (double)s_gi);
            atomicAdd(&g_bc, (double)s_bc);
            atomicAdd(&g_hc, (double)s_hc);
            atomicAdd(&g_np, s_np);
        }
    }

    // ================ last-block finalize ==================================
    if (tid == 0) {
        __threadfence();
        unsigned old = atomicAdd(&g_done, 1u);
        if (old == (unsigned)(NBLK - 1)) {
            __threadfence();
            double cen = g_cen, ced = g_ced, hmb = g_hm;
            double l1s = g_l1, gis = g_gi, bcs = g_bc, hcs = g_hc;
            int nps = g_np;
            // reset for next graph replay
            g_cen = 0.0; g_ced = 0.0; g_hm = 0.0;
            g_l1 = 0.0; g_gi = 0.0; g_bc = 0.0; g_hc = 0.0;
            g_np = 0; g_done = 0;

            double ce   = cen / ced;
            double bbox = l1s / (double)NPAIR;
            double giou = gis / (double)NPAIR;
            double np   = (double)(nps > 0 ? nps : 1);
            double hml  = (hmb + hcs) / np;
            double bxl  = bcs / np;
            double aux  = hml + 5.0 * bxl;
            out[0] = (float)ce;
            out[1] = (float)bbox;
            out[2] = (float)giou;
            out[3] = (float)aux;
            out[4] = (float)(1.0 * ce + 5.0 * bbox + 2.0 * giou + 1.0 * aux);
        }
    }
}

extern "C" void kernel_launch(void* const* d_in, const int* in_sizes, int n_in,
                              void* d_out, int out_size)
{
    const float* pred_logits  = (const float*)d_in[0];
    const float* pred_boxes   = (const float*)d_in[1];
    const float* heatmap      = (const float*)d_in[2];
    const float* box_map      = (const float*)d_in[3];
    const float* tgt_boxes    = (const float*)d_in[4];
    const int*   tgt_labels   = (const int*)d_in[5];
    const float* tgt_sizes    = (const float*)d_in[6];
    const int*   src_idx      = (const int*)d_in[7];
    const int*   tgt_idx      = (const int*)d_in[8];
    const float* empty_weight = (const float*)d_in[9];
    float* out = (float*)d_out;

    long nvec = (long)in_sizes[2] / 4;

    k_all<<<NBLK, THREADS>>>((const float4*)heatmap, nvec,
                             pred_logits, pred_boxes, tgt_boxes, tgt_sizes,
                             src_idx, tgt_idx, tgt_labels, empty_weight,
                             heatmap, box_map, out);
}